// round 5
// baseline (speedup 1.0000x reference)
#include <cuda_runtime.h>
#include <math.h>

#define EPSF 1e-5f

// leaky_relu(z, 0.01) == 0.505*z + 0.495*|z|
__device__ __forceinline__ float lrelu(float z) {
    return fmaf(0.495f, fabsf(z), 0.505f * z);
}

__global__ __launch_bounds__(256) void netlocal_kernel(
    const float* __restrict__ x0g,   // [B,T,3]
    const float* __restrict__ xg,    // [B,T,ND,3]
    const int*   __restrict__ Ng,    // [B,T]
    const float* __restrict__ basisg,// [B,3,3]
    const float* __restrict__ vg,    // [B,T,ND,3]
    const float* __restrict__ Pg,    // [B]
    const float* __restrict__ W0,    // [19,127]
    const float* __restrict__ b0,    // [127]
    const float* __restrict__ W1,    // [128,128]
    const float* __restrict__ b1,    // [128]
    const float* __restrict__ W2,    // [128,128]
    const float* __restrict__ b2,    // [128]
    float*       __restrict__ outg,  // [B,T,128]
    int T, int ND)
{
    const int bt  = blockIdx.x;
    const int b   = bt / T;
    const int tid = threadIdx.x;

    // sp first + explicitly 16B-aligned: it is read via LDS.128 (float4).
    __shared__ __align__(16) float sp[256 * 12]; // per-particle features, float4-padded
    __shared__ float sbasis[9];
    __shared__ float fblk[10];   // block-constant features f4..f13
    __shared__ float sv0[3];
    __shared__ float wsum[8][3];
    __shared__ float pool[256];
    __shared__ float sh[128];
    __shared__ float sh1[128];

    if (tid < 9) sbasis[tid] = basisg[b * 9 + tid];

    const float* vbase = vg + (size_t)bt * ND * 3;
    const float* xbase = xg + (size_t)bt * ND * 3;

    // ---- Phase A: v0 = mean over ND (deterministic tree reduction) ----
    float vx = 0.f, vy = 0.f, vz = 0.f;
    for (int n = tid; n < ND; n += 256) {
        vx += vbase[n * 3 + 0];
        vy += vbase[n * 3 + 1];
        vz += vbase[n * 3 + 2];
    }
#pragma unroll
    for (int o = 16; o > 0; o >>= 1) {
        vx += __shfl_xor_sync(0xffffffffu, vx, o);
        vy += __shfl_xor_sync(0xffffffffu, vy, o);
        vz += __shfl_xor_sync(0xffffffffu, vz, o);
    }
    if ((tid & 31) == 0) {
        wsum[tid >> 5][0] = vx;
        wsum[tid >> 5][1] = vy;
        wsum[tid >> 5][2] = vz;
    }
    __syncthreads();

    if (tid == 0) {
        float sx = 0.f, sy = 0.f, sz = 0.f;
#pragma unroll
        for (int w = 0; w < 8; w++) { sx += wsum[w][0]; sy += wsum[w][1]; sz += wsum[w][2]; }
        const float invN = 1.0f / (float)ND;
        const float v0x = sx * invN, v0y = sy * invN, v0z = sz * invN;
        sv0[0] = v0x; sv0[1] = v0y; sv0[2] = v0z;

        const float x00 = x0g[bt * 3 + 0], x01 = x0g[bt * 3 + 1], x02 = x0g[bt * 3 + 2];
        const float x0n = sqrtf(x00 * x00 + x01 * x01 + x02 * x02) + EPSF;
        const float ix  = 1.0f / x0n;
        const float x0ux = x00 * ix, x0uy = x01 * ix, x0uz = x02 * ix;

        const float v0n = sqrtf(v0x * v0x + v0y * v0y + v0z * v0z) + EPSF;
        const float iv  = 1.0f / v0n;
        const float v0ux = v0x * iv, v0uy = v0y * iv, v0uz = v0z * iv;

        fblk[0] = log1pf((float)Ng[bt]);                                   // f4
        fblk[1] = x0n;                                                     // f5
        fblk[2] = x0ux * sbasis[0] + x0uy * sbasis[1] + x0uz * sbasis[2];  // f6
        fblk[3] = x0ux * sbasis[3] + x0uy * sbasis[4] + x0uz * sbasis[5];  // f7
        fblk[4] = x0ux * sbasis[6] + x0uy * sbasis[7] + x0uz * sbasis[8];  // f8
        fblk[5] = v0n;                                                     // f9
        fblk[6] = v0ux * sbasis[0] + v0uy * sbasis[1] + v0uz * sbasis[2];  // f10
        fblk[7] = v0ux * sbasis[3] + v0uy * sbasis[4] + v0uz * sbasis[5];  // f11
        fblk[8] = v0ux * sbasis[6] + v0uy * sbasis[7] + v0uz * sbasis[8];  // f12
        fblk[9] = x0ux * v0ux + x0uy * v0uy + x0uz * v0uz;                 // f13
    }
    __syncthreads();

    // ---- Phase B: per-particle features (9 of them) into shared ----
    {
        const float v0x = sv0[0], v0y = sv0[1], v0z = sv0[2];
        const float bx0 = sbasis[0], bx1 = sbasis[1], bx2 = sbasis[2];
        const float by0 = sbasis[3], by1 = sbasis[4], by2 = sbasis[5];
        const float bz0 = sbasis[6], bz1 = sbasis[7], bz2 = sbasis[8];
        for (int n = tid; n < ND; n += 256) {
            const float ax = xbase[n * 3 + 0], ay = xbase[n * 3 + 1], az = xbase[n * 3 + 2];
            const float xn = sqrtf(ax * ax + ay * ay + az * az) + EPSF;
            const float ir = 1.0f / xn;
            const float xux = ax * ir, xuy = ay * ir, xuz = az * ir;

            const float wx = vbase[n * 3 + 0] - v0x;
            const float wy = vbase[n * 3 + 1] - v0y;
            const float wz = vbase[n * 3 + 2] - v0z;
            const float vn = sqrtf(wx * wx + wy * wy + wz * wz) + EPSF;
            const float ivn = 1.0f / vn;
            const float vux = wx * ivn, vuy = wy * ivn, vuz = wz * ivn;

            float* p = sp + n * 12;
            p[0] = xn;                                   // f0
            p[1] = xux * bx0 + xuy * bx1 + xuz * bx2;    // f1
            p[2] = xux * by0 + xuy * by1 + xuz * by2;    // f2
            p[3] = xux * bz0 + xuy * bz1 + xuz * bz2;    // f3
            p[4] = vn;                                   // f14
            p[5] = vux * bx0 + vuy * bx1 + vuz * bx2;    // f15
            p[6] = vux * by0 + vuy * by1 + vuz * by2;    // f16
            p[7] = vux * bz0 + vuy * bz1 + vuz * bz2;    // f17
            p[8] = xux * vux + xuy * vuy + xuz * vuz;    // f18
            p[9] = 0.f; p[10] = 0.f; p[11] = 0.f;
        }
    }
    __syncthreads();

    // ---- Phase C: MLP0 + mean pool. 2 halves x 128 columns ----
    {
        const int j    = tid & 127;
        const int half = tid >> 7;
        float w[9];
        float zc = 0.f;
        if (j < 127) {
            // per-particle feature rows of W0: {0,1,2,3,14,15,16,17,18}
            w[0] = W0[0 * 127 + j];
            w[1] = W0[1 * 127 + j];
            w[2] = W0[2 * 127 + j];
            w[3] = W0[3 * 127 + j];
            w[4] = W0[14 * 127 + j];
            w[5] = W0[15 * 127 + j];
            w[6] = W0[16 * 127 + j];
            w[7] = W0[17 * 127 + j];
            w[8] = W0[18 * 127 + j];
            zc = b0[j];
#pragma unroll
            for (int i = 0; i < 10; i++) zc = fmaf(fblk[i], W0[(4 + i) * 127 + j], zc);
        } else {
#pragma unroll
            for (int i = 0; i < 9; i++) w[i] = 0.f;
        }

        float acc = 0.f;
        const float4* sp4 = (const float4*)sp;
#pragma unroll 4
        for (int n = half; n < ND; n += 2) {
            const float4 a = sp4[n * 3 + 0];
            const float4 c = sp4[n * 3 + 1];
            const float4 d = sp4[n * 3 + 2];
            float z = zc;
            z = fmaf(w[0], a.x, z);
            z = fmaf(w[1], a.y, z);
            z = fmaf(w[2], a.z, z);
            z = fmaf(w[3], a.w, z);
            z = fmaf(w[4], c.x, z);
            z = fmaf(w[5], c.y, z);
            z = fmaf(w[6], c.z, z);
            z = fmaf(w[7], c.w, z);
            z = fmaf(w[8], d.x, z);
            acc += lrelu(z);
        }
        pool[tid] = acc;
    }
    __syncthreads();

    if (tid < 128) {
        const float pm = (pool[tid] + pool[tid + 128]) * (1.0f / (float)ND);
        sh[tid] = (tid < 127) ? pm : fblk[0];   // append log1p(N) at index 127
    }
    __syncthreads();

    // ---- Phase D: h @ W1 (+lrelu), then @ W2, scale by 1/P200c ----
    if (tid < 128) {
        float a1 = b1[tid];
#pragma unroll 8
        for (int k = 0; k < 128; k++) a1 = fmaf(sh[k], W1[k * 128 + tid], a1);
        sh1[tid] = lrelu(a1);
    }
    __syncthreads();
    if (tid < 128) {
        float a2 = b2[tid];
#pragma unroll 8
        for (int k = 0; k < 128; k++) a2 = fmaf(sh1[k], W2[k * 128 + tid], a2);
        outg[(size_t)bt * 128 + tid] = a2 * (1.0f / Pg[b]);
    }
}

extern "C" void kernel_launch(void* const* d_in, const int* in_sizes, int n_in,
                              void* d_out, int out_size) {
    const float* x0g    = (const float*)d_in[0];
    const float* xg     = (const float*)d_in[1];
    const int*   Ng     = (const int*)  d_in[2];
    const float* basisg = (const float*)d_in[3];
    const float* vg     = (const float*)d_in[4];
    const float* Pg     = (const float*)d_in[5];
    const float* W0     = (const float*)d_in[6];
    const float* b0     = (const float*)d_in[7];
    const float* W1     = (const float*)d_in[8];
    const float* b1     = (const float*)d_in[9];
    const float* W2     = (const float*)d_in[10];
    const float* b2     = (const float*)d_in[11];
    float* outg = (float*)d_out;

    const int B  = in_sizes[5];                       // P200c: [B]
    const int BT = in_sizes[2];                       // N: [B,T]
    const int T  = BT / B;
    const int ND = in_sizes[1] / (BT * 3);            // x: [B,T,ND,3]

    netlocal_kernel<<<BT, 256>>>(x0g, xg, Ng, basisg, vg, Pg,
                                 W0, b0, W1, b1, W2, b2, outg, T, ND);
}

// round 6
// speedup vs baseline: 1.1653x; 1.1653x over previous
#include <cuda_runtime.h>
#include <math.h>

#define EPSF 1e-5f

// leaky_relu(z, 0.01) == 0.505*z + 0.495*|z|
__device__ __forceinline__ float lrelu(float z) {
    return fmaf(0.495f, fabsf(z), 0.505f * z);
}

__global__ __launch_bounds__(256) void netlocal_kernel(
    const float* __restrict__ x0g,   // [B,T,3]
    const float* __restrict__ xg,    // [B,T,ND,3]
    const int*   __restrict__ Ng,    // [B,T]
    const float* __restrict__ basisg,// [B,3,3]
    const float* __restrict__ vg,    // [B,T,ND,3]
    const float* __restrict__ Pg,    // [B]
    const float* __restrict__ W0,    // [19,127]
    const float* __restrict__ b0,    // [127]
    const float* __restrict__ W1,    // [128,128]
    const float* __restrict__ b1,    // [128]
    const float* __restrict__ W2,    // [128,128]
    const float* __restrict__ b2,    // [128]
    float*       __restrict__ outg,  // [B,T,128]
    int T, int ND)
{
    const int bt  = blockIdx.x;
    const int b   = bt / T;
    const int tid = threadIdx.x;

    // sp is read via LDS.128 — must be 16B aligned.
    __shared__ __align__(16) float sp[256 * 12]; // per-particle features, float4-padded
    __shared__ float sbasis[9];
    __shared__ float fblk[10];   // block-constant features f4..f13
    __shared__ float sv0[3];
    __shared__ float wsum[8][3];
    __shared__ float poolp[128 * 9];  // [col][warp], stride 9 = conflict-free
    __shared__ float sh[128];
    __shared__ float sh1[128];
    __shared__ float partial[256];

    if (tid < 9) sbasis[tid] = basisg[b * 9 + tid];

    const float* vbase = vg + (size_t)bt * ND * 3;
    const float* xbase = xg + (size_t)bt * ND * 3;

    // ---- Phase A: v0 = mean over ND (deterministic tree reduction) ----
    float vx = 0.f, vy = 0.f, vz = 0.f;
    for (int n = tid; n < ND; n += 256) {
        vx += vbase[n * 3 + 0];
        vy += vbase[n * 3 + 1];
        vz += vbase[n * 3 + 2];
    }
#pragma unroll
    for (int o = 16; o > 0; o >>= 1) {
        vx += __shfl_xor_sync(0xffffffffu, vx, o);
        vy += __shfl_xor_sync(0xffffffffu, vy, o);
        vz += __shfl_xor_sync(0xffffffffu, vz, o);
    }
    if ((tid & 31) == 0) {
        wsum[tid >> 5][0] = vx;
        wsum[tid >> 5][1] = vy;
        wsum[tid >> 5][2] = vz;
    }
    __syncthreads();

    if (tid == 0) {
        float sx = 0.f, sy = 0.f, sz = 0.f;
#pragma unroll
        for (int w = 0; w < 8; w++) { sx += wsum[w][0]; sy += wsum[w][1]; sz += wsum[w][2]; }
        const float invN = 1.0f / (float)ND;
        const float v0x = sx * invN, v0y = sy * invN, v0z = sz * invN;
        sv0[0] = v0x; sv0[1] = v0y; sv0[2] = v0z;

        const float x00 = x0g[bt * 3 + 0], x01 = x0g[bt * 3 + 1], x02 = x0g[bt * 3 + 2];
        const float x0n = sqrtf(x00 * x00 + x01 * x01 + x02 * x02) + EPSF;
        const float ix  = 1.0f / x0n;
        const float x0ux = x00 * ix, x0uy = x01 * ix, x0uz = x02 * ix;

        const float v0n = sqrtf(v0x * v0x + v0y * v0y + v0z * v0z) + EPSF;
        const float iv  = 1.0f / v0n;
        const float v0ux = v0x * iv, v0uy = v0y * iv, v0uz = v0z * iv;

        fblk[0] = log1pf((float)Ng[bt]);                                   // f4
        fblk[1] = x0n;                                                     // f5
        fblk[2] = x0ux * sbasis[0] + x0uy * sbasis[1] + x0uz * sbasis[2];  // f6
        fblk[3] = x0ux * sbasis[3] + x0uy * sbasis[4] + x0uz * sbasis[5];  // f7
        fblk[4] = x0ux * sbasis[6] + x0uy * sbasis[7] + x0uz * sbasis[8];  // f8
        fblk[5] = v0n;                                                     // f9
        fblk[6] = v0ux * sbasis[0] + v0uy * sbasis[1] + v0uz * sbasis[2];  // f10
        fblk[7] = v0ux * sbasis[3] + v0uy * sbasis[4] + v0uz * sbasis[5];  // f11
        fblk[8] = v0ux * sbasis[6] + v0uy * sbasis[7] + v0uz * sbasis[8];  // f12
        fblk[9] = x0ux * v0ux + x0uy * v0uy + x0uz * v0uz;                 // f13
    }
    __syncthreads();

    // ---- Phase B: per-particle features (9 of them) into shared ----
    {
        const float v0x = sv0[0], v0y = sv0[1], v0z = sv0[2];
        const float bx0 = sbasis[0], bx1 = sbasis[1], bx2 = sbasis[2];
        const float by0 = sbasis[3], by1 = sbasis[4], by2 = sbasis[5];
        const float bz0 = sbasis[6], bz1 = sbasis[7], bz2 = sbasis[8];
        for (int n = tid; n < ND; n += 256) {
            const float ax = xbase[n * 3 + 0], ay = xbase[n * 3 + 1], az = xbase[n * 3 + 2];
            const float xn = sqrtf(ax * ax + ay * ay + az * az) + EPSF;
            const float ir = 1.0f / xn;
            const float xux = ax * ir, xuy = ay * ir, xuz = az * ir;

            const float wx = vbase[n * 3 + 0] - v0x;
            const float wy = vbase[n * 3 + 1] - v0y;
            const float wz = vbase[n * 3 + 2] - v0z;
            const float vn = sqrtf(wx * wx + wy * wy + wz * wz) + EPSF;
            const float ivn = 1.0f / vn;
            const float vux = wx * ivn, vuy = wy * ivn, vuz = wz * ivn;

            float* p = sp + n * 12;
            p[0] = xn;                                   // f0
            p[1] = xux * bx0 + xuy * bx1 + xuz * bx2;    // f1
            p[2] = xux * by0 + xuy * by1 + xuz * by2;    // f2
            p[3] = xux * bz0 + xuy * bz1 + xuz * bz2;    // f3
            p[4] = vn;                                   // f14
            p[5] = vux * bx0 + vuy * bx1 + vuz * bx2;    // f15
            p[6] = vux * by0 + vuy * by1 + vuz * by2;    // f16
            p[7] = vux * bz0 + vuy * bz1 + vuz * bz2;    // f17
            p[8] = xux * vux + xuy * vuy + xuz * vuz;    // f18
            p[9] = 0.f; p[10] = 0.f; p[11] = 0.f;
        }
    }
    __syncthreads();

    // ---- Phase C: MLP0 + mean pool. Each lane: 4 columns; each warp: ND/8 particles ----
    {
        const int g = tid & 31;   // base column
        const int w = tid >> 5;   // warp id = particle slice
        float wr[4][9];
        float zc[4];
#pragma unroll
        for (int c = 0; c < 4; c++) {
            const int j = g + 32 * c;
            if (j < 127) {
                // per-particle feature rows of W0: {0,1,2,3,14,15,16,17,18}
                wr[c][0] = W0[0 * 127 + j];
                wr[c][1] = W0[1 * 127 + j];
                wr[c][2] = W0[2 * 127 + j];
                wr[c][3] = W0[3 * 127 + j];
                wr[c][4] = W0[14 * 127 + j];
                wr[c][5] = W0[15 * 127 + j];
                wr[c][6] = W0[16 * 127 + j];
                wr[c][7] = W0[17 * 127 + j];
                wr[c][8] = W0[18 * 127 + j];
                float z = b0[j];
#pragma unroll
                for (int i = 0; i < 10; i++) z = fmaf(fblk[i], W0[(4 + i) * 127 + j], z);
                zc[c] = z;
            } else {
#pragma unroll
                for (int i = 0; i < 9; i++) wr[c][i] = 0.f;
                zc[c] = 0.f;
            }
        }

        const int nw = ND >> 3;            // particles per warp slice
        const int n0 = w * nw;
        float acc[4] = {0.f, 0.f, 0.f, 0.f};
        const float4* sp4 = (const float4*)(sp) + (size_t)n0 * 3;
#pragma unroll 2
        for (int i = 0; i < nw; i++) {
            const float4 a = sp4[i * 3 + 0];
            const float4 cc = sp4[i * 3 + 1];
            const float4 d = sp4[i * 3 + 2];
#pragma unroll
            for (int c = 0; c < 4; c++) {
                float z = zc[c];
                z = fmaf(wr[c][0], a.x, z);
                z = fmaf(wr[c][1], a.y, z);
                z = fmaf(wr[c][2], a.z, z);
                z = fmaf(wr[c][3], a.w, z);
                z = fmaf(wr[c][4], cc.x, z);
                z = fmaf(wr[c][5], cc.y, z);
                z = fmaf(wr[c][6], cc.z, z);
                z = fmaf(wr[c][7], cc.w, z);
                z = fmaf(wr[c][8], d.x, z);
                acc[c] += lrelu(z);
            }
        }
#pragma unroll
        for (int c = 0; c < 4; c++)
            poolp[(g + 32 * c) * 9 + w] = acc[c];
    }
    __syncthreads();

    if (tid < 128) {
        float s = 0.f;
#pragma unroll
        for (int w = 0; w < 8; w++) s += poolp[tid * 9 + w];
        const float pm = s * (1.0f / (float)ND);
        sh[tid] = (tid < 127) ? pm : fblk[0];   // append log1p(N) at index 127
    }
    __syncthreads();

    // ---- Phase D: h @ W1 (+lrelu), then @ W2, scale by 1/P200c. Split-k over 256 threads ----
    {
        const int j = tid & 127;
        const int h = tid >> 7;       // k-half
        float a1 = (h == 0) ? b1[j] : 0.f;
        const int k0 = h * 64;
#pragma unroll 8
        for (int k = k0; k < k0 + 64; k++) a1 = fmaf(sh[k], W1[k * 128 + j], a1);
        partial[tid] = a1;
    }
    __syncthreads();
    if (tid < 128) sh1[tid] = lrelu(partial[tid] + partial[tid + 128]);
    __syncthreads();
    {
        const int j = tid & 127;
        const int h = tid >> 7;
        float a2 = (h == 0) ? b2[j] : 0.f;
        const int k0 = h * 64;
#pragma unroll 8
        for (int k = k0; k < k0 + 64; k++) a2 = fmaf(sh1[k], W2[k * 128 + j], a2);
        partial[tid] = a2;
    }
    __syncthreads();
    if (tid < 128) {
        outg[(size_t)bt * 128 + tid] =
            (partial[tid] + partial[tid + 128]) * (1.0f / Pg[b]);
    }
}

extern "C" void kernel_launch(void* const* d_in, const int* in_sizes, int n_in,
                              void* d_out, int out_size) {
    const float* x0g    = (const float*)d_in[0];
    const float* xg     = (const float*)d_in[1];
    const int*   Ng     = (const int*)  d_in[2];
    const float* basisg = (const float*)d_in[3];
    const float* vg     = (const float*)d_in[4];
    const float* Pg     = (const float*)d_in[5];
    const float* W0     = (const float*)d_in[6];
    const float* b0     = (const float*)d_in[7];
    const float* W1     = (const float*)d_in[8];
    const float* b1     = (const float*)d_in[9];
    const float* W2     = (const float*)d_in[10];
    const float* b2     = (const float*)d_in[11];
    float* outg = (float*)d_out;

    const int B  = in_sizes[5];                       // P200c: [B]
    const int BT = in_sizes[2];                       // N: [B,T]
    const int T  = BT / B;
    const int ND = in_sizes[1] / (BT * 3);            // x: [B,T,ND,3]

    netlocal_kernel<<<BT, 256>>>(x0g, xg, Ng, basisg, vg, Pg,
                                 W0, b0, W1, b1, W2, b2, outg, T, ND);
}

// round 8
// speedup vs baseline: 1.3608x; 1.1677x over previous
#include <cuda_runtime.h>
#include <math.h>

#define EPSF 1e-5f

typedef unsigned long long ull;

// leaky_relu(z, 0.01) == 0.505*z + 0.495*|z|
__device__ __forceinline__ float lrelu(float z) {
    return fmaf(0.495f, fabsf(z), 0.505f * z);
}

// packed helpers (sm_103a f32x2 pipe)
#define FMA2(acc, a, b) \
    asm("fma.rn.f32x2 %0, %1, %2, %0;" : "+l"(acc) : "l"(a), "l"(b))
#define AND2(d, s, m) \
    asm("and.b64 %0, %1, %2;" : "=l"(d) : "l"(s), "l"(m))
#define PACK2(d, x) \
    asm("mov.b64 %0, {%1, %1};" : "=l"(d) : "r"(__float_as_uint(x)))
#define PACK2U(d, x) \
    asm("mov.b64 %0, {%1, %1};" : "=l"(d) : "r"(x))
#define UNPACK2(lo, hi, s) \
    asm("mov.b64 {%0, %1}, %2;" : "=r"(lo), "=r"(hi) : "l"(s))

#define SPT_STR 256   // feature-major row stride (ND <= 256)

__global__ __launch_bounds__(256) void netlocal_kernel(
    const float* __restrict__ x0g,   // [B,T,3]
    const float* __restrict__ xg,    // [B,T,ND,3]
    const int*   __restrict__ Ng,    // [B,T]
    const float* __restrict__ basisg,// [B,3,3]
    const float* __restrict__ vg,    // [B,T,ND,3]
    const float* __restrict__ Pg,    // [B]
    const float* __restrict__ W0,    // [19,127]
    const float* __restrict__ b0,    // [127]
    const float* __restrict__ W1,    // [128,128]
    const float* __restrict__ b1,    // [128]
    const float* __restrict__ W2,    // [128,128]
    const float* __restrict__ b2,    // [128]
    float*       __restrict__ outg,  // [B,T,128]
    int T, int ND)
{
    const int bt  = blockIdx.x;
    const int b   = bt / T;
    const int tid = threadIdx.x;

    // feature-major: spT[k][n], read via 16B LDS broadcast
    __shared__ __align__(16) float spT[9 * SPT_STR];
    __shared__ float sbasis[9];
    __shared__ float fblk[10];   // block-constant features f4..f13
    __shared__ float sv0[3];
    __shared__ float wsum[8][3];
    __shared__ float poolp[128 * 5];  // [col][slice], stride 5 = conflict-free
    __shared__ float sh[128];
    __shared__ float sh1[128];
    __shared__ float partial[256];

    if (tid < 9) sbasis[tid] = basisg[b * 9 + tid];

    const float* vbase = vg + (size_t)bt * ND * 3;
    const float* xbase = xg + (size_t)bt * ND * 3;

    // ---- Phase A: v0 = mean over ND (deterministic tree reduction) ----
    float vx = 0.f, vy = 0.f, vz = 0.f;
    for (int n = tid; n < ND; n += 256) {
        vx += vbase[n * 3 + 0];
        vy += vbase[n * 3 + 1];
        vz += vbase[n * 3 + 2];
    }
#pragma unroll
    for (int o = 16; o > 0; o >>= 1) {
        vx += __shfl_xor_sync(0xffffffffu, vx, o);
        vy += __shfl_xor_sync(0xffffffffu, vy, o);
        vz += __shfl_xor_sync(0xffffffffu, vz, o);
    }
    if ((tid & 31) == 0) {
        wsum[tid >> 5][0] = vx;
        wsum[tid >> 5][1] = vy;
        wsum[tid >> 5][2] = vz;
    }
    __syncthreads();

    if (tid == 0) {
        float sx = 0.f, sy = 0.f, sz = 0.f;
#pragma unroll
        for (int w = 0; w < 8; w++) { sx += wsum[w][0]; sy += wsum[w][1]; sz += wsum[w][2]; }
        const float invN = 1.0f / (float)ND;
        const float v0x = sx * invN, v0y = sy * invN, v0z = sz * invN;
        sv0[0] = v0x; sv0[1] = v0y; sv0[2] = v0z;

        const float x00 = x0g[bt * 3 + 0], x01 = x0g[bt * 3 + 1], x02 = x0g[bt * 3 + 2];
        const float x0n = sqrtf(x00 * x00 + x01 * x01 + x02 * x02) + EPSF;
        const float ix  = 1.0f / x0n;
        const float x0ux = x00 * ix, x0uy = x01 * ix, x0uz = x02 * ix;

        const float v0n = sqrtf(v0x * v0x + v0y * v0y + v0z * v0z) + EPSF;
        const float iv  = 1.0f / v0n;
        const float v0ux = v0x * iv, v0uy = v0y * iv, v0uz = v0z * iv;

        fblk[0] = log1pf((float)Ng[bt]);                                   // f4
        fblk[1] = x0n;                                                     // f5
        fblk[2] = x0ux * sbasis[0] + x0uy * sbasis[1] + x0uz * sbasis[2];  // f6
        fblk[3] = x0ux * sbasis[3] + x0uy * sbasis[4] + x0uz * sbasis[5];  // f7
        fblk[4] = x0ux * sbasis[6] + x0uy * sbasis[7] + x0uz * sbasis[8];  // f8
        fblk[5] = v0n;                                                     // f9
        fblk[6] = v0ux * sbasis[0] + v0uy * sbasis[1] + v0uz * sbasis[2];  // f10
        fblk[7] = v0ux * sbasis[3] + v0uy * sbasis[4] + v0uz * sbasis[5];  // f11
        fblk[8] = v0ux * sbasis[6] + v0uy * sbasis[7] + v0uz * sbasis[8];  // f12
        fblk[9] = x0ux * v0ux + x0uy * v0uy + x0uz * v0uz;                 // f13
    }
    __syncthreads();

    // ---- Phase B: per-particle features (9) into feature-major shared ----
    {
        const float v0x = sv0[0], v0y = sv0[1], v0z = sv0[2];
        const float bx0 = sbasis[0], bx1 = sbasis[1], bx2 = sbasis[2];
        const float by0 = sbasis[3], by1 = sbasis[4], by2 = sbasis[5];
        const float bz0 = sbasis[6], bz1 = sbasis[7], bz2 = sbasis[8];
        for (int n = tid; n < ND; n += 256) {
            const float ax = xbase[n * 3 + 0], ay = xbase[n * 3 + 1], az = xbase[n * 3 + 2];
            const float xn = sqrtf(ax * ax + ay * ay + az * az) + EPSF;
            const float ir = 1.0f / xn;
            const float xux = ax * ir, xuy = ay * ir, xuz = az * ir;

            const float wx = vbase[n * 3 + 0] - v0x;
            const float wy = vbase[n * 3 + 1] - v0y;
            const float wz = vbase[n * 3 + 2] - v0z;
            const float vn = sqrtf(wx * wx + wy * wy + wz * wz) + EPSF;
            const float ivn = 1.0f / vn;
            const float vux = wx * ivn, vuy = wy * ivn, vuz = wz * ivn;

            spT[0 * SPT_STR + n] = xn;                                 // f0
            spT[1 * SPT_STR + n] = xux * bx0 + xuy * bx1 + xuz * bx2;  // f1
            spT[2 * SPT_STR + n] = xux * by0 + xuy * by1 + xuz * by2;  // f2
            spT[3 * SPT_STR + n] = xux * bz0 + xuy * bz1 + xuz * bz2;  // f3
            spT[4 * SPT_STR + n] = vn;                                 // f14
            spT[5 * SPT_STR + n] = vux * bx0 + vuy * bx1 + vuz * bx2;  // f15
            spT[6 * SPT_STR + n] = vux * by0 + vuy * by1 + vuz * by2;  // f16
            spT[7 * SPT_STR + n] = vux * bz0 + vuy * bz1 + vuz * bz2;  // f17
            spT[8 * SPT_STR + n] = xux * vux + xuy * vuy + xuz * vuz;  // f18
        }
    }
    __syncthreads();

    // ---- Phase C: MLP0 + mean pool, packed f32x2 (2 particles/lane-slot) ----
    // tid -> columns {j, j+64} (j = tid&63), particle slice s = tid>>6 (warp-uniform).
    {
        const int j = tid & 63;
        const int s = tid >> 6;

        ull w2[2][9];
        ull zc2[2];
#pragma unroll
        for (int c = 0; c < 2; c++) {
            const int col = j + 64 * c;
            float wr[9], zv;
            if (col < 127) {
                // per-particle feature rows of W0: {0,1,2,3,14,15,16,17,18}
                wr[0] = W0[0 * 127 + col];
                wr[1] = W0[1 * 127 + col];
                wr[2] = W0[2 * 127 + col];
                wr[3] = W0[3 * 127 + col];
                wr[4] = W0[14 * 127 + col];
                wr[5] = W0[15 * 127 + col];
                wr[6] = W0[16 * 127 + col];
                wr[7] = W0[17 * 127 + col];
                wr[8] = W0[18 * 127 + col];
                zv = b0[col];
#pragma unroll
                for (int i = 0; i < 10; i++) zv = fmaf(fblk[i], W0[(4 + i) * 127 + col], zv);
            } else {
#pragma unroll
                for (int i = 0; i < 9; i++) wr[i] = 0.f;
                zv = 0.f;
            }
#pragma unroll
            for (int i = 0; i < 9; i++) PACK2(w2[c][i], wr[i]);
            PACK2(zc2[c], zv);
        }

        ull c505, c495, mabs;
        PACK2(c505, 0.505f);
        PACK2(c495, 0.495f);
        PACK2U(mabs, 0x7FFFFFFFu);

        const int nspl = ND >> 2;       // particles per slice
        const int n0b  = s * nspl;
        ull acc[2][2] = {{0ull, 0ull}, {0ull, 0ull}};  // [col][pair]

        for (int i = 0; i < nspl; i += 4) {
            const int n0 = n0b + i;
            ull z00 = zc2[0], z01 = zc2[0], z10 = zc2[1], z11 = zc2[1];
#pragma unroll
            for (int k = 0; k < 9; k++) {
                // one broadcast LDS.128: features of particles n0..n0+3
                const ulonglong2 q =
                    *(const ulonglong2*)(spT + k * SPT_STR + n0);
                FMA2(z00, w2[0][k], q.x);
                FMA2(z01, w2[0][k], q.y);
                FMA2(z10, w2[1][k], q.x);
                FMA2(z11, w2[1][k], q.y);
            }
            ull a;
            AND2(a, z00, mabs); FMA2(acc[0][0], c505, z00); FMA2(acc[0][0], c495, a);
            AND2(a, z01, mabs); FMA2(acc[0][1], c505, z01); FMA2(acc[0][1], c495, a);
            AND2(a, z10, mabs); FMA2(acc[1][0], c505, z10); FMA2(acc[1][0], c495, a);
            AND2(a, z11, mabs); FMA2(acc[1][1], c505, z11); FMA2(acc[1][1], c495, a);
        }

#pragma unroll
        for (int c = 0; c < 2; c++) {
            unsigned int l0, h0, l1, h1;
            UNPACK2(l0, h0, acc[c][0]);
            UNPACK2(l1, h1, acc[c][1]);
            const float tot = (__uint_as_float(l0) + __uint_as_float(h0)) +
                              (__uint_as_float(l1) + __uint_as_float(h1));
            poolp[(j + 64 * c) * 5 + s] = tot;
        }
    }
    __syncthreads();

    if (tid < 128) {
        float sm = 0.f;
#pragma unroll
        for (int w = 0; w < 4; w++) sm += poolp[tid * 5 + w];
        const float pm = sm * (1.0f / (float)ND);
        sh[tid] = (tid < 127) ? pm : fblk[0];   // append log1p(N) at index 127
    }
    __syncthreads();

    // ---- Phase D: h @ W1 (+lrelu), then @ W2, scale by 1/P200c. Split-k ----
    {
        const int j = tid & 127;
        const int h = tid >> 7;       // k-half
        float a1 = (h == 0) ? b1[j] : 0.f;
        const int k0 = h * 64;
#pragma unroll 8
        for (int k = k0; k < k0 + 64; k++) a1 = fmaf(sh[k], W1[k * 128 + j], a1);
        partial[tid] = a1;
    }
    __syncthreads();
    if (tid < 128) sh1[tid] = lrelu(partial[tid] + partial[tid + 128]);
    __syncthreads();
    {
        const int j = tid & 127;
        const int h = tid >> 7;
        float a2 = (h == 0) ? b2[j] : 0.f;
        const int k0 = h * 64;
#pragma unroll 8
        for (int k = k0; k < k0 + 64; k++) a2 = fmaf(sh1[k], W2[k * 128 + j], a2);
        partial[tid] = a2;
    }
    __syncthreads();
    if (tid < 128) {
        outg[(size_t)bt * 128 + tid] =
            (partial[tid] + partial[tid + 128]) * (1.0f / Pg[b]);
    }
}

extern "C" void kernel_launch(void* const* d_in, const int* in_sizes, int n_in,
                              void* d_out, int out_size) {
    const float* x0g    = (const float*)d_in[0];
    const float* xg     = (const float*)d_in[1];
    const int*   Ng     = (const int*)  d_in[2];
    const float* basisg = (const float*)d_in[3];
    const float* vg     = (const float*)d_in[4];
    const float* Pg     = (const float*)d_in[5];
    const float* W0     = (const float*)d_in[6];
    const float* b0     = (const float*)d_in[7];
    const float* W1     = (const float*)d_in[8];
    const float* b1     = (const float*)d_in[9];
    const float* W2     = (const float*)d_in[10];
    const float* b2     = (const float*)d_in[11];
    float* outg = (float*)d_out;

    const int B  = in_sizes[5];                       // P200c: [B]
    const int BT = in_sizes[2];                       // N: [B,T]
    const int T  = BT / B;
    const int ND = in_sizes[1] / (BT * 3);            // x: [B,T,ND,3]

    netlocal_kernel<<<BT, 256>>>(x0g, xg, Ng, basisg, vg, Pg,
                                 W0, b0, W1, b1, W2, b2, outg, T, ND);
}